// round 8
// baseline (speedup 1.0000x reference)
#include <cuda_runtime.h>
#include <cuda_bf16.h>
#include <cstdint>

// Problem constants
constexpr int NB  = 2;    // batch
constexpr int NN  = 768;  // nodes
constexpr int NU  = 64;   // embed dim
constexpr int NK  = 8;    // relation dim
constexpr int NIN = 136;  // 2U + K
constexpr int NPD = 160;  // padded hidden (5 per lane * 32 lanes)
constexpr int MAXE = NN * NN;
constexpr float SLOPE = 0.01f;

// ---------------- device scratch ----------------
__device__ unsigned char g_mask[NN * NN];
__device__ float g_invD[NN];
__device__ int   g_colcnt[NN];
__device__ int   g_colstart[NN];
__device__ int   g_totE;
__device__ int2  g_eij[MAXE];          // flat edge -> (i, j), column-grouped
__device__ float g_edgeval[NB * MAXE];
__device__ float g_A   [NB * NN * NPD];
__device__ float g_Base[NB * NN * NPD];
__device__ float g_x1  [NB * NN * NU];

// ---------------- kernel 1: mask + row degree + invD ----------------
__global__ void maskdeg_kernel(const float* __restrict__ rel) {
    int i = blockIdx.x;
    int tid = threadIdx.x;
    int cnt = 0;
    for (int j = tid; j < NN; j += 256) {
        const float4* p = reinterpret_cast<const float4*>(rel + ((size_t)i * NN + j) * NK);
        float4 a = p[0], b = p[1];
        float s = a.x + a.y + a.z + a.w + b.x + b.y + b.z + b.w;
        unsigned char m = (s > 0.0f) ? 1 : 0;
        g_mask[i * NN + j] = m;
        cnt += m;
    }
    #pragma unroll
    for (int o = 16; o > 0; o >>= 1) cnt += __shfl_xor_sync(~0u, cnt, o);
    __shared__ int wsum[8];
    if ((tid & 31) == 0) wsum[tid >> 5] = cnt;
    __syncthreads();
    if (tid == 0) {
        int t = 0;
        #pragma unroll
        for (int w = 0; w < 8; w++) t += wsum[w];
        g_invD[i] = 1.0f / (float)(t > 0 ? t : 1);
    }
}

// ---------------- kernel 2: per-column counts (ballot) ----------------
__global__ void colcnt_kernel() {
    int j = blockIdx.x;
    int tid = threadIdx.x;          // row i
    int lane = tid & 31;
    int flag = g_mask[tid * NN + j];
    unsigned bal = __ballot_sync(~0u, flag != 0);
    __shared__ int wcnt[24];
    if (lane == 0) wcnt[tid >> 5] = __popc(bal);
    __syncthreads();
    if (tid == 0) {
        int acc = 0;
        #pragma unroll
        for (int w = 0; w < 24; w++) acc += wcnt[w];
        g_colcnt[j] = acc;
    }
}

// ---------------- kernel 3: build compact edge list (fused scan) ----------------
__global__ void build_kernel() {
    int j = blockIdx.x;
    int tid = threadIdx.x;          // row i
    int warp = tid >> 5, lane = tid & 31;

    int cv = (tid < j) ? g_colcnt[tid] : 0;
    #pragma unroll
    for (int o = 16; o > 0; o >>= 1) cv += __shfl_xor_sync(~0u, cv, o);
    __shared__ int wred[24];
    __shared__ int s_st;
    if (lane == 0) wred[warp] = cv;
    __syncthreads();
    if (tid == 0) {
        int st = 0;
        #pragma unroll
        for (int w = 0; w < 24; w++) st += wred[w];
        s_st = st;
        g_colstart[j] = st;
    }

    int flag = g_mask[tid * NN + j];
    unsigned bal = __ballot_sync(~0u, flag != 0);
    __shared__ int wcnt[24];
    __shared__ int wpre[25];
    if (lane == 0) wcnt[warp] = __popc(bal);
    __syncthreads();
    if (tid == 0) {
        int acc = 0;
        #pragma unroll
        for (int w = 0; w < 24; w++) { wpre[w] = acc; acc += wcnt[w]; }
        wpre[24] = acc;
        if (j == NN - 1) g_totE = s_st + acc;
    }
    __syncthreads();
    if (flag) {
        int pos = wpre[warp] + __popc(bal & ((1u << lane) - 1u));
        g_eij[s_st + pos] = make_int2(tid, j);
    }
}

// ---------------- precompute GEMM core (RPB=8, 4-way k-split, 640 threads) ----------------
constexpr int RPB = 8;   // rows per block
constexpr int KH  = 4;   // k-splits
constexpr int UPK = NU / KH;   // 16 u's per split
constexpr int PTHREADS = NPD * KH;  // 640

__device__ __forceinline__ void precompute_core(
    const float (*sx)[NU],
    float (*spA)[RPB][NPD], float (*spB)[RPB][NPD],   // [KH-1][RPB][NPD]
    int R0, int tid,
    const float* __restrict__ W1, const float* __restrict__ b1)
{
    int n  = tid % NPD;
    int kh = tid / NPD;            // 0..3 (warp-uniform)
    float a[RPB], bs[RPB];
    #pragma unroll
    for (int r = 0; r < RPB; r++) { a[r] = 0.0f; bs[r] = 0.0f; }
    if (n < NIN) {
        int ub = kh * UPK;
        #pragma unroll 4
        for (int u0 = 0; u0 < UPK; u0++) {
            int u = ub + u0;
            float wa = W1[u * NIN + n];
            float wb = W1[(NU + u) * NIN + n];
            #pragma unroll
            for (int r = 0; r < RPB; r++) {
                a[r]  = fmaf(sx[r][u], wa, a[r]);
                bs[r] = fmaf(sx[r][u], wb, bs[r]);
            }
        }
    }
    if (kh > 0) {
        #pragma unroll
        for (int r = 0; r < RPB; r++) {
            spA[kh - 1][r][n] = a[r];
            spB[kh - 1][r][n] = bs[r];
        }
    }
    __syncthreads();
    if (kh == 0) {
        float bb = (n < NIN) ? b1[n] : 0.0f;
        #pragma unroll
        for (int r = 0; r < RPB; r++) {
            float av = a[r]  + spA[0][r][n] + spA[1][r][n] + spA[2][r][n];
            float bv = bs[r] + spB[0][r][n] + spB[1][r][n] + spB[2][r][n];
            g_A   [(size_t)(R0 + r) * NPD + n] = av;
            g_Base[(size_t)(R0 + r) * NPD + n] = bv + bb;
        }
    }
}

// ---------------- kernel 4: precompute hop 1 ----------------
__global__ void __launch_bounds__(PTHREADS) precompute_kernel(
    const float* __restrict__ xp,
    const float* __restrict__ W1,
    const float* __restrict__ b1) {
    __shared__ float sx[RPB][NU];
    __shared__ float spA[KH - 1][RPB][NPD];
    __shared__ float spB[KH - 1][RPB][NPD];
    int R0 = blockIdx.x * RPB;
    int tid = threadIdx.x;
    for (int idx = tid; idx < RPB * NU; idx += PTHREADS)
        sx[idx >> 6][idx & 63] = xp[(size_t)R0 * NU + idx];
    __syncthreads();
    precompute_core(sx, spA, spB, R0, tid, W1, b1);
}

// ---------------- kernel 4b: fused hop1-reduce + hop2-precompute ----------------
__global__ void __launch_bounds__(PTHREADS) precompute_fused_kernel(
    const float* __restrict__ seq,
    const float* __restrict__ W1,
    const float* __restrict__ b1) {
    __shared__ float sx[RPB][NU];
    __shared__ float spA[KH - 1][RPB][NPD];
    __shared__ float spB[KH - 1][RPB][NPD];
    int R0 = blockIdx.x * RPB;
    int tid = threadIdx.x;
    int warp = tid >> 5, lane = tid & 31;

    if (warp < RPB) {   // warp r reduces pair R0+r, builds x1 = x0 * S
        int p = R0 + warp;
        int b = p / NN, j = p % NN;
        int st = g_colstart[j], c = g_colcnt[j];
        const float* ev = g_edgeval + (size_t)b * MAXE + st;
        float s = 0.0f;
        for (int e = lane; e < c; e += 32) s += ev[e];
        #pragma unroll
        for (int o = 16; o > 0; o >>= 1) s += __shfl_xor_sync(~0u, s, o);
        size_t base = (size_t)p * NU;
        float v0 = seq[base + lane]      * s;
        float v1 = seq[base + 32 + lane] * s;
        sx[warp][lane]      = v0;
        sx[warp][lane + 32] = v1;
        g_x1[base + lane]      = v0;
        g_x1[base + 32 + lane] = v1;
    }
    __syncthreads();
    precompute_core(sx, spA, spB, R0, tid, W1, b1);
}

// ---------------- kernel 5: flat edge phase ----------------
__global__ void __launch_bounds__(256, 3) edge_kernel(
    const float* __restrict__ rel,
    const float* __restrict__ W1,
    const float* __restrict__ w2,
    const float* __restrict__ b2p)
{
    __shared__ float sW1c[NK * NPD];

    int tid = threadIdx.x, warp = tid >> 5, lane = tid & 31;

    for (int idx = tid; idx < NK * NPD; idx += 256) {
        int kk = idx / NPD, n = idx % NPD;
        sW1c[idx] = (n < NIN) ? W1[(2 * NU + kk) * NIN + n] : 0.0f;
    }
    float w2l[5];
    #pragma unroll
    for (int m = 0; m < 5; m++) {
        int n = lane + 32 * m;
        w2l[m] = (n < NIN) ? w2[n] : 0.0f;
    }
    float b2 = __ldg(b2p);
    __syncthreads();

    int totE = g_totE;
    int nPairs = (totE + 1) >> 1;
    int gw = blockIdx.x * 8 + warp;
    int nw = gridDim.x * 8;

    for (int P = gw; P < nPairs; P += nw) {
        int e0 = P << 1;
        int  ev[2];
        bool valid[2];
        float vdv[2];
        float rv[2][8];
        float h[4][5];      // chain c = s*2 + b

        #pragma unroll
        for (int s = 0; s < 2; s++) {
            int e = e0 + s;
            valid[s] = (e < totE);
            if (!valid[s]) e = totE - 1;
            ev[s] = e;
            int2 eij = g_eij[e];
            int i = eij.x, j = eij.y;
            vdv[s] = g_invD[i];
            const float4* rp = reinterpret_cast<const float4*>(
                rel + ((size_t)i * NN + j) * NK);
            float4 r0 = rp[0], r1 = rp[1];
            rv[s][0] = r0.x; rv[s][1] = r0.y; rv[s][2] = r0.z; rv[s][3] = r0.w;
            rv[s][4] = r1.x; rv[s][5] = r1.y; rv[s][6] = r1.z; rv[s][7] = r1.w;
            #pragma unroll
            for (int b = 0; b < 2; b++) {
                const float* Ar = g_A    + ((size_t)(b * NN + i)) * NPD;
                const float* Br = g_Base + ((size_t)(b * NN + j)) * NPD;
                #pragma unroll
                for (int m = 0; m < 5; m++)
                    h[s * 2 + b][m] = Ar[lane + 32 * m] + Br[lane + 32 * m];
            }
        }

        #pragma unroll
        for (int kk = 0; kk < NK; kk++) {
            float w1v[5];
            #pragma unroll
            for (int m = 0; m < 5; m++)
                w1v[m] = sW1c[kk * NPD + lane + 32 * m];
            #pragma unroll
            for (int c = 0; c < 4; c++)
                #pragma unroll
                for (int m = 0; m < 5; m++)
                    h[c][m] = fmaf(rv[c >> 1][kk], w1v[m], h[c][m]);
        }

        float d[4];
        #pragma unroll
        for (int c = 0; c < 4; c++) {
            float acc = 0.0f;
            #pragma unroll
            for (int m = 0; m < 5; m++) {
                float hv = h[c][m];
                hv = fmaxf(hv, SLOPE * hv);
                acc = fmaf(hv, w2l[m], acc);
            }
            d[c] = acc;
        }
        #pragma unroll
        for (int o = 16; o > 0; o >>= 1) {
            #pragma unroll
            for (int c = 0; c < 4; c++)
                d[c] += __shfl_xor_sync(~0u, d[c], o);
        }
        #pragma unroll
        for (int c = 0; c < 4; c++) {
            int s = c >> 1, b = c & 1;
            float o2 = d[c] + b2;
            o2 = fmaxf(o2, SLOPE * o2);
            float val = o2 * vdv[s];
            if (lane == c && valid[s])
                g_edgeval[b * MAXE + ev[s]] = val;
        }
    }
}

// ---------------- kernel 6: final column reduce + output scale ----------------
__global__ void reduce_scale_kernel(float* __restrict__ xout) {
    int gw = blockIdx.x * (blockDim.x >> 5) + (threadIdx.x >> 5);
    if (gw >= NB * NN) return;
    int lane = threadIdx.x & 31;
    int b = gw / NN, j = gw % NN;
    int st = g_colstart[j], c = g_colcnt[j];
    const float* ev = g_edgeval + (size_t)b * MAXE + st;
    float s = 0.0f;
    for (int e = lane; e < c; e += 32) s += ev[e];
    #pragma unroll
    for (int o = 16; o > 0; o >>= 1) s += __shfl_xor_sync(~0u, s, o);
    size_t base = (size_t)gw * NU;
    xout[base + lane]      = g_x1[base + lane]      * s;
    xout[base + 32 + lane] = g_x1[base + 32 + lane] * s;
}

// ---------------- launch ----------------
extern "C" void kernel_launch(void* const* d_in, const int* in_sizes, int n_in,
                              void* d_out, int out_size) {
    const float* seq  = (const float*)d_in[0];
    const float* rel  = (const float*)d_in[1];
    const float* w1_1 = (const float*)d_in[2];
    const float* b1_1 = (const float*)d_in[3];
    const float* w1_2 = (const float*)d_in[4];
    const float* b1_2 = (const float*)d_in[5];
    const float* w2_1 = (const float*)d_in[6];
    const float* b2_1 = (const float*)d_in[7];
    const float* w2_2 = (const float*)d_in[8];
    const float* b2_2 = (const float*)d_in[9];
    float* out = (float*)d_out;

    maskdeg_kernel<<<NN, 256>>>(rel);
    colcnt_kernel <<<NN, 768>>>();
    build_kernel  <<<NN, 768>>>();

    const int PGRID = NB * NN / RPB;   // 192
    const int EGRID = 444;
    const int RGRID = (NB * NN + 7) / 8;

    // hop 1
    precompute_kernel<<<PGRID, PTHREADS>>>(seq, w1_1, b1_1);
    edge_kernel      <<<EGRID, 256>>>(rel, w1_1, w1_2, b1_2);

    // hop 2 (reduce of hop 1 fused into precompute)
    precompute_fused_kernel<<<PGRID, PTHREADS>>>(seq, w2_1, b2_1);
    edge_kernel      <<<EGRID, 256>>>(rel, w2_1, w2_2, b2_2);
    reduce_scale_kernel<<<RGRID, 256>>>(out);
}

// round 9
// speedup vs baseline: 1.0005x; 1.0005x over previous
#include <cuda_runtime.h>
#include <cuda_bf16.h>
#include <cstdint>

// Problem constants
constexpr int NB  = 2;    // batch
constexpr int NN  = 768;  // nodes
constexpr int NU  = 64;   // embed dim
constexpr int NK  = 8;    // relation dim
constexpr int NIN = 136;  // 2U + K
constexpr int NPD = 160;  // padded hidden (5 per lane * 32 lanes)
constexpr int MAXE = NN * NN;
constexpr float SLOPE = 0.01f;

// precompute tiling
constexpr int RPB = 6;                 // pairs per block (1536/6 = 256 blocks)
constexpr int KH  = 2;                 // k-split
constexpr int PTHREADS = NPD * KH;     // 320
constexpr int W1AB = 2 * NU * NIN;     // 17408 floats staged
// dynamic smem: sW1[W1AB] | sx[RPB][NU] | spA[RPB][NPD] | spB[RPB][NPD]
constexpr int SM_SX  = W1AB;
constexpr int SM_SPA = SM_SX + RPB * NU;
constexpr int SM_SPB = SM_SPA + RPB * NPD;
constexpr int PRE_SMEM_FLOATS = SM_SPB + RPB * NPD;
constexpr int PRE_SMEM_BYTES  = PRE_SMEM_FLOATS * 4;   // 78,848 B

// ---------------- device scratch ----------------
__device__ unsigned char g_mask[NN * NN];
__device__ float g_invD[NN];
__device__ int   g_colcnt[NN];
__device__ int   g_colstart[NN];
__device__ int   g_totE;
__device__ int2  g_eij[MAXE];          // flat edge -> (i, j), column-grouped
__device__ float g_edgeval[NB * MAXE];
__device__ float g_A   [NB * NN * NPD];
__device__ float g_Base[NB * NN * NPD];
__device__ float g_x1  [NB * NN * NU];

// ---------------- kernel 1: mask + row degree + invD ----------------
__global__ void maskdeg_kernel(const float* __restrict__ rel) {
    int i = blockIdx.x;
    int tid = threadIdx.x;
    int cnt = 0;
    for (int j = tid; j < NN; j += 256) {
        const float4* p = reinterpret_cast<const float4*>(rel + ((size_t)i * NN + j) * NK);
        float4 a = p[0], b = p[1];
        float s = a.x + a.y + a.z + a.w + b.x + b.y + b.z + b.w;
        unsigned char m = (s > 0.0f) ? 1 : 0;
        g_mask[i * NN + j] = m;
        cnt += m;
    }
    #pragma unroll
    for (int o = 16; o > 0; o >>= 1) cnt += __shfl_xor_sync(~0u, cnt, o);
    __shared__ int wsum[8];
    if ((tid & 31) == 0) wsum[tid >> 5] = cnt;
    __syncthreads();
    if (tid == 0) {
        int t = 0;
        #pragma unroll
        for (int w = 0; w < 8; w++) t += wsum[w];
        g_invD[i] = 1.0f / (float)(t > 0 ? t : 1);
    }
}

// ---------------- kernel 2: per-column counts (ballot) ----------------
__global__ void colcnt_kernel() {
    int j = blockIdx.x;
    int tid = threadIdx.x;          // row i
    int lane = tid & 31;
    int flag = g_mask[tid * NN + j];
    unsigned bal = __ballot_sync(~0u, flag != 0);
    __shared__ int wcnt[24];
    if (lane == 0) wcnt[tid >> 5] = __popc(bal);
    __syncthreads();
    if (tid == 0) {
        int acc = 0;
        #pragma unroll
        for (int w = 0; w < 24; w++) acc += wcnt[w];
        g_colcnt[j] = acc;
    }
}

// ---------------- kernel 3: build compact edge list (fused scan) ----------------
__global__ void build_kernel() {
    int j = blockIdx.x;
    int tid = threadIdx.x;          // row i
    int warp = tid >> 5, lane = tid & 31;

    int cv = (tid < j) ? g_colcnt[tid] : 0;
    #pragma unroll
    for (int o = 16; o > 0; o >>= 1) cv += __shfl_xor_sync(~0u, cv, o);
    __shared__ int wred[24];
    __shared__ int s_st;
    if (lane == 0) wred[warp] = cv;
    __syncthreads();
    if (tid == 0) {
        int st = 0;
        #pragma unroll
        for (int w = 0; w < 24; w++) st += wred[w];
        s_st = st;
        g_colstart[j] = st;
    }

    int flag = g_mask[tid * NN + j];
    unsigned bal = __ballot_sync(~0u, flag != 0);
    __shared__ int wcnt[24];
    __shared__ int wpre[25];
    if (lane == 0) wcnt[warp] = __popc(bal);
    __syncthreads();
    if (tid == 0) {
        int acc = 0;
        #pragma unroll
        for (int w = 0; w < 24; w++) { wpre[w] = acc; acc += wcnt[w]; }
        wpre[24] = acc;
        if (j == NN - 1) g_totE = s_st + acc;
    }
    __syncthreads();
    if (flag) {
        int pos = wpre[warp] + __popc(bal & ((1u << lane) - 1u));
        g_eij[s_st + pos] = make_int2(tid, j);
    }
}

// ---------------- precompute GEMM core (W1 in smem, KH=2) ----------------
__device__ __forceinline__ void precompute_core(
    float* sm, int R0, int tid,
    const float* __restrict__ b1)
{
    const float* sW1 = sm;
    const float (*sx)[NU] = (const float(*)[NU])(sm + SM_SX);
    float* spA = sm + SM_SPA;
    float* spB = sm + SM_SPB;

    int n  = tid % NPD;
    int kh = tid / NPD;            // 0..1 (warp-uniform)
    float a[RPB], bs[RPB];
    #pragma unroll
    for (int r = 0; r < RPB; r++) { a[r] = 0.0f; bs[r] = 0.0f; }
    if (n < NIN) {
        int ub = kh * 32;
        #pragma unroll 8
        for (int u0 = 0; u0 < 32; u0++) {
            int u = ub + u0;
            float wa = sW1[u * NIN + n];
            float wb = sW1[(NU + u) * NIN + n];
            #pragma unroll
            for (int r = 0; r < RPB; r++) {
                a[r]  = fmaf(sx[r][u], wa, a[r]);
                bs[r] = fmaf(sx[r][u], wb, bs[r]);
            }
        }
    }
    if (kh == 1) {
        #pragma unroll
        for (int r = 0; r < RPB; r++) {
            spA[r * NPD + n] = a[r];
            spB[r * NPD + n] = bs[r];
        }
    }
    __syncthreads();
    if (kh == 0) {
        float bb = (n < NIN) ? b1[n] : 0.0f;
        #pragma unroll
        for (int r = 0; r < RPB; r++) {
            g_A   [(size_t)(R0 + r) * NPD + n] = a[r] + spA[r * NPD + n];
            g_Base[(size_t)(R0 + r) * NPD + n] = bs[r] + spB[r * NPD + n] + bb;
        }
    }
}

// ---------------- kernel 4: precompute hop 1 ----------------
__global__ void __launch_bounds__(PTHREADS) precompute_kernel(
    const float* __restrict__ xp,
    const float* __restrict__ W1,
    const float* __restrict__ b1) {
    extern __shared__ float sm[];
    int R0 = blockIdx.x * RPB;
    int tid = threadIdx.x;
    // stage W1ab
    for (int idx = tid; idx < W1AB; idx += PTHREADS)
        sm[idx] = W1[idx];
    // stage x rows
    float* sx = sm + SM_SX;
    for (int idx = tid; idx < RPB * NU; idx += PTHREADS)
        sx[idx] = xp[(size_t)R0 * NU + idx];
    __syncthreads();
    precompute_core(sm, R0, tid, b1);
}

// ---------------- kernel 4b: fused hop1-reduce + hop2-precompute ----------------
__global__ void __launch_bounds__(PTHREADS) precompute_fused_kernel(
    const float* __restrict__ seq,
    const float* __restrict__ W1,
    const float* __restrict__ b1) {
    extern __shared__ float sm[];
    int R0 = blockIdx.x * RPB;
    int tid = threadIdx.x;
    int warp = tid >> 5, lane = tid & 31;

    // stage W1ab (all threads)
    for (int idx = tid; idx < W1AB; idx += PTHREADS)
        sm[idx] = W1[idx];

    // warps 0..RPB-1: reduce pair R0+warp, build x1 = x0 * S into sx & g_x1
    float* sx = sm + SM_SX;
    if (warp < RPB) {
        int p = R0 + warp;
        int b = p / NN, j = p % NN;
        int st = g_colstart[j], c = g_colcnt[j];
        const float* ev = g_edgeval + (size_t)b * MAXE + st;
        float s = 0.0f;
        for (int e = lane; e < c; e += 32) s += ev[e];
        #pragma unroll
        for (int o = 16; o > 0; o >>= 1) s += __shfl_xor_sync(~0u, s, o);
        size_t base = (size_t)p * NU;
        float v0 = seq[base + lane]      * s;
        float v1 = seq[base + 32 + lane] * s;
        sx[warp * NU + lane]      = v0;
        sx[warp * NU + lane + 32] = v1;
        g_x1[base + lane]      = v0;
        g_x1[base + 32 + lane] = v1;
    }
    __syncthreads();
    precompute_core(sm, R0, tid, b1);
}

// ---------------- kernel 5: flat edge phase ----------------
__global__ void __launch_bounds__(256, 3) edge_kernel(
    const float* __restrict__ rel,
    const float* __restrict__ W1,
    const float* __restrict__ w2,
    const float* __restrict__ b2p)
{
    __shared__ float sW1c[NK * NPD];

    int tid = threadIdx.x, warp = tid >> 5, lane = tid & 31;

    for (int idx = tid; idx < NK * NPD; idx += 256) {
        int kk = idx / NPD, n = idx % NPD;
        sW1c[idx] = (n < NIN) ? W1[(2 * NU + kk) * NIN + n] : 0.0f;
    }
    float w2l[5];
    #pragma unroll
    for (int m = 0; m < 5; m++) {
        int n = lane + 32 * m;
        w2l[m] = (n < NIN) ? w2[n] : 0.0f;
    }
    float b2 = __ldg(b2p);
    __syncthreads();

    int totE = g_totE;
    int nPairs = (totE + 1) >> 1;
    int gw = blockIdx.x * 8 + warp;
    int nw = gridDim.x * 8;

    for (int P = gw; P < nPairs; P += nw) {
        int e0 = P << 1;
        int  ev[2];
        bool valid[2];
        float vdv[2];
        float rv[2][8];
        float h[4][5];      // chain c = s*2 + b

        #pragma unroll
        for (int s = 0; s < 2; s++) {
            int e = e0 + s;
            valid[s] = (e < totE);
            if (!valid[s]) e = totE - 1;
            ev[s] = e;
            int2 eij = g_eij[e];
            int i = eij.x, j = eij.y;
            vdv[s] = g_invD[i];
            const float4* rp = reinterpret_cast<const float4*>(
                rel + ((size_t)i * NN + j) * NK);
            float4 r0 = rp[0], r1 = rp[1];
            rv[s][0] = r0.x; rv[s][1] = r0.y; rv[s][2] = r0.z; rv[s][3] = r0.w;
            rv[s][4] = r1.x; rv[s][5] = r1.y; rv[s][6] = r1.z; rv[s][7] = r1.w;
            #pragma unroll
            for (int b = 0; b < 2; b++) {
                const float* Ar = g_A    + ((size_t)(b * NN + i)) * NPD;
                const float* Br = g_Base + ((size_t)(b * NN + j)) * NPD;
                #pragma unroll
                for (int m = 0; m < 5; m++)
                    h[s * 2 + b][m] = Ar[lane + 32 * m] + Br[lane + 32 * m];
            }
        }

        #pragma unroll
        for (int kk = 0; kk < NK; kk++) {
            float w1v[5];
            #pragma unroll
            for (int m = 0; m < 5; m++)
                w1v[m] = sW1c[kk * NPD + lane + 32 * m];
            #pragma unroll
            for (int c = 0; c < 4; c++)
                #pragma unroll
                for (int m = 0; m < 5; m++)
                    h[c][m] = fmaf(rv[c >> 1][kk], w1v[m], h[c][m]);
        }

        float d[4];
        #pragma unroll
        for (int c = 0; c < 4; c++) {
            float acc = 0.0f;
            #pragma unroll
            for (int m = 0; m < 5; m++) {
                float hv = h[c][m];
                hv = fmaxf(hv, SLOPE * hv);
                acc = fmaf(hv, w2l[m], acc);
            }
            d[c] = acc;
        }
        #pragma unroll
        for (int o = 16; o > 0; o >>= 1) {
            #pragma unroll
            for (int c = 0; c < 4; c++)
                d[c] += __shfl_xor_sync(~0u, d[c], o);
        }
        #pragma unroll
        for (int c = 0; c < 4; c++) {
            int s = c >> 1, b = c & 1;
            float o2 = d[c] + b2;
            o2 = fmaxf(o2, SLOPE * o2);
            float val = o2 * vdv[s];
            if (lane == c && valid[s])
                g_edgeval[b * MAXE + ev[s]] = val;
        }
    }
}

// ---------------- kernel 6: final column reduce + output scale ----------------
__global__ void reduce_scale_kernel(float* __restrict__ xout) {
    int gw = blockIdx.x * (blockDim.x >> 5) + (threadIdx.x >> 5);
    if (gw >= NB * NN) return;
    int lane = threadIdx.x & 31;
    int b = gw / NN, j = gw % NN;
    int st = g_colstart[j], c = g_colcnt[j];
    const float* ev = g_edgeval + (size_t)b * MAXE + st;
    float s = 0.0f;
    for (int e = lane; e < c; e += 32) s += ev[e];
    #pragma unroll
    for (int o = 16; o > 0; o >>= 1) s += __shfl_xor_sync(~0u, s, o);
    size_t base = (size_t)gw * NU;
    xout[base + lane]      = g_x1[base + lane]      * s;
    xout[base + 32 + lane] = g_x1[base + 32 + lane] * s;
}

// ---------------- launch ----------------
extern "C" void kernel_launch(void* const* d_in, const int* in_sizes, int n_in,
                              void* d_out, int out_size) {
    const float* seq  = (const float*)d_in[0];
    const float* rel  = (const float*)d_in[1];
    const float* w1_1 = (const float*)d_in[2];
    const float* b1_1 = (const float*)d_in[3];
    const float* w1_2 = (const float*)d_in[4];
    const float* b1_2 = (const float*)d_in[5];
    const float* w2_1 = (const float*)d_in[6];
    const float* b2_1 = (const float*)d_in[7];
    const float* w2_2 = (const float*)d_in[8];
    const float* b2_2 = (const float*)d_in[9];
    float* out = (float*)d_out;

    cudaFuncSetAttribute(precompute_kernel,
        cudaFuncAttributeMaxDynamicSharedMemorySize, PRE_SMEM_BYTES);
    cudaFuncSetAttribute(precompute_fused_kernel,
        cudaFuncAttributeMaxDynamicSharedMemorySize, PRE_SMEM_BYTES);

    maskdeg_kernel<<<NN, 256>>>(rel);
    colcnt_kernel <<<NN, 768>>>();
    build_kernel  <<<NN, 768>>>();

    const int PGRID = NB * NN / RPB;   // 256
    const int EGRID = 444;
    const int RGRID = (NB * NN + 7) / 8;

    // hop 1
    precompute_kernel<<<PGRID, PTHREADS, PRE_SMEM_BYTES>>>(seq, w1_1, b1_1);
    edge_kernel      <<<EGRID, 256>>>(rel, w1_1, w1_2, b1_2);

    // hop 2 (reduce of hop 1 fused into precompute)
    precompute_fused_kernel<<<PGRID, PTHREADS, PRE_SMEM_BYTES>>>(seq, w2_1, b2_1);
    edge_kernel      <<<EGRID, 256>>>(rel, w2_1, w2_2, b2_2);
    reduce_scale_kernel<<<RGRID, 256>>>(out);
}

// round 10
// speedup vs baseline: 1.0272x; 1.0267x over previous
#include <cuda_runtime.h>
#include <cuda_bf16.h>
#include <cstdint>

// Problem constants
constexpr int NB  = 2;    // batch
constexpr int NN  = 768;  // nodes
constexpr int NU  = 64;   // embed dim
constexpr int NK  = 8;    // relation dim
constexpr int NIN = 136;  // 2U + K
constexpr int NPD = 160;  // padded hidden (5 per lane * 32 lanes)
constexpr float SLOPE = 0.01f;

// precompute tiling
constexpr int PNT = 80;                // float2 n-threads (160 padded cols / 2)
constexpr int PKH = 4;                 // k splits (16 u's each)
constexpr int PTHREADS = PNT * PKH;    // 320
constexpr int RPB = 4;                 // rows per block -> grid 384

// ---------------- device scratch ----------------
__device__ int   g_Dint[NN];
__device__ float g_invD[NN];
__device__ int   g_colcnt[NN];
__device__ int   g_colrows[NN * NN];   // per-column row lists (i-ordered)
__device__ float g_A   [NB * NN * NPD];
__device__ float g_Base[NB * NN * NPD];
__device__ float g_x1  [NB * NN * NU];

// ---------------- kernel 1: zero row degrees ----------------
__global__ void zeroD_kernel() {
    int i = threadIdx.x;
    if (i < NN) g_Dint[i] = 0;
}

// ---------------- kernel 2: column lists + counts + row degrees ----------------
__global__ void colbuild_kernel(const float* __restrict__ rel) {
    int j = blockIdx.x;
    int i = threadIdx.x;            // row
    int warp = i >> 5, lane = i & 31;

    const float4* rp = reinterpret_cast<const float4*>(rel + ((size_t)i * NN + j) * NK);
    float4 a = rp[0], b = rp[1];
    float s = a.x + a.y + a.z + a.w + b.x + b.y + b.z + b.w;
    int flag = (s > 0.0f) ? 1 : 0;

    unsigned bal = __ballot_sync(~0u, flag != 0);
    __shared__ int wcnt[24];
    __shared__ int wpre[25];
    if (lane == 0) wcnt[warp] = __popc(bal);
    __syncthreads();
    if (i == 0) {
        int acc = 0;
        #pragma unroll
        for (int w = 0; w < 24; w++) { wpre[w] = acc; acc += wcnt[w]; }
        wpre[24] = acc;
        g_colcnt[j] = acc;
    }
    __syncthreads();
    if (flag) {
        int pos = wpre[warp] + __popc(bal & ((1u << lane) - 1u));
        g_colrows[j * NN + pos] = i;
        atomicAdd(&g_Dint[i], 1);   // integer: deterministic
    }
}

// ---------------- kernel 3: precompute A, Base (float2, 4-way k-split) ----------------
__global__ void __launch_bounds__(PTHREADS) precompute_kernel(
    const float* __restrict__ xext, int use_g,
    const float* __restrict__ W1,
    const float* __restrict__ b1,
    int do_invd)
{
    const float* xp = use_g ? g_x1 : xext;
    __shared__ float sx[RPB][NU];
    __shared__ float spA[PKH - 1][RPB][NPD];
    __shared__ float spB[PKH - 1][RPB][NPD];
    int tid = threadIdx.x;
    int R0 = blockIdx.x * RPB;

    if (do_invd && blockIdx.x == 0) {
        for (int i = tid; i < NN; i += PTHREADS) {
            int d = g_Dint[i];
            g_invD[i] = 1.0f / (float)(d > 0 ? d : 1);
        }
    }

    for (int idx = tid; idx < RPB * NU; idx += PTHREADS)
        sx[idx >> 6][idx & 63] = xp[(size_t)R0 * NU + idx];
    __syncthreads();

    int nt = tid % PNT;          // float2 column pair
    int kh = tid / PNT;          // 0..3
    int n0 = nt * 2;

    float ax[RPB], ay[RPB], bx[RPB], by[RPB];
    #pragma unroll
    for (int r = 0; r < RPB; r++) { ax[r] = ay[r] = bx[r] = by[r] = 0.0f; }

    if (nt < 68) {               // n0 <= 134 < NIN
        int ub = kh * 16;
        #pragma unroll
        for (int u0 = 0; u0 < 16; u0++) {
            int u = ub + u0;
            float2 wa = *reinterpret_cast<const float2*>(W1 + (size_t)u * NIN + n0);
            float2 wb = *reinterpret_cast<const float2*>(W1 + (size_t)(NU + u) * NIN + n0);
            #pragma unroll
            for (int r = 0; r < RPB; r++) {
                float xv = sx[r][u];
                ax[r] = fmaf(xv, wa.x, ax[r]);
                ay[r] = fmaf(xv, wa.y, ay[r]);
                bx[r] = fmaf(xv, wb.x, bx[r]);
                by[r] = fmaf(xv, wb.y, by[r]);
            }
        }
    }
    if (kh > 0) {
        #pragma unroll
        for (int r = 0; r < RPB; r++) {
            spA[kh - 1][r][n0]     = ax[r];
            spA[kh - 1][r][n0 + 1] = ay[r];
            spB[kh - 1][r][n0]     = bx[r];
            spB[kh - 1][r][n0 + 1] = by[r];
        }
    }
    __syncthreads();
    if (kh == 0) {
        float bb0 = (nt < 68) ? b1[n0]     : 0.0f;
        float bb1 = (nt < 68) ? b1[n0 + 1] : 0.0f;
        #pragma unroll
        for (int r = 0; r < RPB; r++) {
            float A0 = ax[r] + spA[0][r][n0]     + spA[1][r][n0]     + spA[2][r][n0];
            float A1 = ay[r] + spA[0][r][n0 + 1] + spA[1][r][n0 + 1] + spA[2][r][n0 + 1];
            float B0 = bx[r] + spB[0][r][n0]     + spB[1][r][n0]     + spB[2][r][n0];
            float B1 = by[r] + spB[0][r][n0 + 1] + spB[1][r][n0 + 1] + spB[2][r][n0 + 1];
            size_t o = (size_t)(R0 + r) * NPD + n0;
            g_A[o]        = A0;
            g_A[o + 1]    = A1;
            g_Base[o]     = B0 + bb0;
            g_Base[o + 1] = B1 + bb1;
        }
    }
}

// ---------------- kernel 4: edge phase, warp per (b,j), writes x_out directly ----------------
__global__ void __launch_bounds__(256) edge_kernel(
    const float* __restrict__ xin_ext, float* __restrict__ xout_ext,
    int use_g_in, int use_g_out,
    const float* __restrict__ rel,
    const float* __restrict__ W1,      // rows 128..135 = rel weights
    const float* __restrict__ w2,
    const float* __restrict__ b2p)
{
    const float* xin  = use_g_in  ? g_x1 : xin_ext;
    float*       xout = use_g_out ? g_x1 : xout_ext;

    __shared__ float sW1c[NK * NPD];
    int tid = threadIdx.x, warp = tid >> 5, lane = tid & 31;

    for (int idx = tid; idx < NK * NPD; idx += 256) {
        int kk = idx / NPD, n = idx % NPD;
        sW1c[idx] = (n < NIN) ? W1[(2 * NU + kk) * NIN + n] : 0.0f;
    }
    float w2l[5];
    #pragma unroll
    for (int m = 0; m < 5; m++) {
        int n = lane + 32 * m;
        w2l[m] = (n < NIN) ? w2[n] : 0.0f;
    }
    float b2 = __ldg(b2p);
    __syncthreads();

    int p = blockIdx.x * 8 + warp;      // exactly NB*NN warps
    int b = p / NN, j = p % NN;
    int cnt = g_colcnt[j];
    const int* rows = g_colrows + j * NN;

    // hoist Base for this (b,j)
    float base[5];
    {
        const float* Bs = g_Base + (size_t)p * NPD;
        #pragma unroll
        for (int m = 0; m < 5; m++) base[m] = Bs[lane + 32 * m];
    }

    float wacc = 0.0f;
    for (int e0 = 0; e0 < cnt; e0 += 4) {
        int4 r4 = *reinterpret_cast<const int4*>(rows + e0);   // 4-aligned, padded row
        int ivr[4] = {r4.x, r4.y, r4.z, r4.w};
        float vdv[4];
        float rv[4][8];
        float h[4][5];

        #pragma unroll
        for (int s = 0; s < 4; s++) {
            bool v = (e0 + s < cnt);
            int i = v ? ivr[s] : 0;
            vdv[s] = v ? g_invD[i] : 0.0f;
            const float4* rp = reinterpret_cast<const float4*>(
                rel + ((size_t)i * NN + j) * NK);
            float4 r0 = rp[0], r1 = rp[1];
            rv[s][0] = r0.x; rv[s][1] = r0.y; rv[s][2] = r0.z; rv[s][3] = r0.w;
            rv[s][4] = r1.x; rv[s][5] = r1.y; rv[s][6] = r1.z; rv[s][7] = r1.w;
            const float* Ar = g_A + ((size_t)(b * NN + i)) * NPD;
            #pragma unroll
            for (int m = 0; m < 5; m++)
                h[s][m] = Ar[lane + 32 * m] + base[m];
        }

        #pragma unroll
        for (int kk = 0; kk < NK; kk++) {
            float w1v[5];
            #pragma unroll
            for (int m = 0; m < 5; m++)
                w1v[m] = sW1c[kk * NPD + lane + 32 * m];
            #pragma unroll
            for (int s = 0; s < 4; s++)
                #pragma unroll
                for (int m = 0; m < 5; m++)
                    h[s][m] = fmaf(rv[s][kk], w1v[m], h[s][m]);
        }

        float d[4];
        #pragma unroll
        for (int s = 0; s < 4; s++) {
            float acc = 0.0f;
            #pragma unroll
            for (int m = 0; m < 5; m++) {
                float hv = h[s][m];
                hv = fmaxf(hv, SLOPE * hv);
                acc = fmaf(hv, w2l[m], acc);
            }
            d[s] = acc;
        }
        #pragma unroll
        for (int o = 16; o > 0; o >>= 1) {
            #pragma unroll
            for (int s = 0; s < 4; s++)
                d[s] += __shfl_xor_sync(~0u, d[s], o);
        }
        #pragma unroll
        for (int s = 0; s < 4; s++) {
            float o2 = d[s] + b2;
            o2 = fmaxf(o2, SLOPE * o2);
            wacc = fmaf(o2, vdv[s], wacc);
        }
    }

    // wacc is warp-uniform; write scaled output directly
    size_t obase = (size_t)p * NU;
    xout[obase + lane]      = xin[obase + lane]      * wacc;
    xout[obase + 32 + lane] = xin[obase + 32 + lane] * wacc;
}

// ---------------- launch ----------------
extern "C" void kernel_launch(void* const* d_in, const int* in_sizes, int n_in,
                              void* d_out, int out_size) {
    const float* seq  = (const float*)d_in[0];
    const float* rel  = (const float*)d_in[1];
    const float* w1_1 = (const float*)d_in[2];
    const float* b1_1 = (const float*)d_in[3];
    const float* w1_2 = (const float*)d_in[4];
    const float* b1_2 = (const float*)d_in[5];
    const float* w2_1 = (const float*)d_in[6];
    const float* b2_1 = (const float*)d_in[7];
    const float* w2_2 = (const float*)d_in[8];
    const float* b2_2 = (const float*)d_in[9];
    float* out = (float*)d_out;

    zeroD_kernel   <<<1, NN>>>();
    colbuild_kernel<<<NN, NN>>>(rel);

    const int PGRID = NB * NN / RPB;   // 384
    const int EGRID = NB * NN / 8;     // 192 blocks x 8 warps = 1536 pairs

    // hop 1: seq -> g_x1
    precompute_kernel<<<PGRID, PTHREADS>>>(seq, 0, w1_1, b1_1, 1);
    edge_kernel      <<<EGRID, 256>>>(seq, nullptr, 0, 1, rel, w1_1, w1_2, b1_2);

    // hop 2: g_x1 -> out
    precompute_kernel<<<PGRID, PTHREADS>>>(nullptr, 1, w2_1, b2_1, 0);
    edge_kernel      <<<EGRID, 256>>>(nullptr, out, 1, 0, rel, w2_1, w2_2, b2_2);
}

// round 11
// speedup vs baseline: 1.0976x; 1.0685x over previous
#include <cuda_runtime.h>
#include <cuda_bf16.h>
#include <cstdint>

// Problem constants
constexpr int NB  = 2;    // batch
constexpr int NN  = 768;  // nodes
constexpr int NU  = 64;   // embed dim
constexpr int NK  = 8;    // relation dim
constexpr int NIN = 136;  // 2U + K
constexpr int NPD = 160;  // padded hidden (5 per lane * 32 lanes)
constexpr float SLOPE = 0.01f;

// precompute tiling (R7 proven shape)
constexpr int RPB = 4;
constexpr int KH  = 2;
constexpr int PTHREADS = NPD * KH;  // 320

// ---------------- device scratch ----------------
__device__ unsigned char g_mask[NN * NN];
__device__ float g_invD[NN];
__device__ int   g_colcnt[NN];
__device__ int   g_colrows[NN * NN];   // per-column row lists (i-ordered)
__device__ float g_A   [NB * NN * NPD];
__device__ float g_Base[NB * NN * NPD];
__device__ float g_x1  [NB * NN * NU];

// ---------------- kernel 1: mask + row degree + invD ----------------
__global__ void maskdeg_kernel(const float* __restrict__ rel) {
    int i = blockIdx.x;
    int tid = threadIdx.x;
    int cnt = 0;
    for (int j = tid; j < NN; j += 256) {
        const float4* p = reinterpret_cast<const float4*>(rel + ((size_t)i * NN + j) * NK);
        float4 a = p[0], b = p[1];
        float s = a.x + a.y + a.z + a.w + b.x + b.y + b.z + b.w;
        unsigned char m = (s > 0.0f) ? 1 : 0;
        g_mask[i * NN + j] = m;
        cnt += m;
    }
    #pragma unroll
    for (int o = 16; o > 0; o >>= 1) cnt += __shfl_xor_sync(~0u, cnt, o);
    __shared__ int wsum[8];
    if ((tid & 31) == 0) wsum[tid >> 5] = cnt;
    __syncthreads();
    if (tid == 0) {
        int t = 0;
        #pragma unroll
        for (int w = 0; w < 8; w++) t += wsum[w];
        g_invD[i] = 1.0f / (float)(t > 0 ? t : 1);
    }
}

// ---------------- kernel 2: per-column lists + counts (ballot compaction) ----------------
__global__ void colbuild_kernel() {
    int j = blockIdx.x;
    int tid = threadIdx.x;          // row i
    int warp = tid >> 5, lane = tid & 31;
    int flag = g_mask[tid * NN + j];
    unsigned bal = __ballot_sync(~0u, flag != 0);
    __shared__ int wcnt[24];
    __shared__ int wpre[25];
    if (lane == 0) wcnt[warp] = __popc(bal);
    __syncthreads();
    if (tid == 0) {
        int acc = 0;
        #pragma unroll
        for (int w = 0; w < 24; w++) { wpre[w] = acc; acc += wcnt[w]; }
        wpre[24] = acc;
        g_colcnt[j] = acc;
    }
    __syncthreads();
    if (flag) {
        int pos = wpre[warp] + __popc(bal & ((1u << lane) - 1u));
        g_colrows[j * NN + pos] = tid;
    }
}

// ---------------- precompute GEMM (R7 proven: KH=2, 320 threads, RPB=4) ----------------
__global__ void __launch_bounds__(PTHREADS) precompute_kernel(
    const float* __restrict__ xext, int use_g,
    const float* __restrict__ W1,
    const float* __restrict__ b1) {
    const float* xp = use_g ? g_x1 : xext;
    __shared__ float sx[RPB][NU];
    __shared__ float spA[RPB][NPD];
    __shared__ float spB[RPB][NPD];
    int R0 = blockIdx.x * RPB;
    int tid = threadIdx.x;
    for (int idx = tid; idx < RPB * NU; idx += PTHREADS)
        sx[idx >> 6][idx & 63] = xp[(size_t)R0 * NU + idx];
    __syncthreads();

    int n  = tid % NPD;
    int kh = tid / NPD;
    float a[RPB], bs[RPB];
    #pragma unroll
    for (int r = 0; r < RPB; r++) { a[r] = 0.0f; bs[r] = 0.0f; }
    if (n < NIN) {
        int ub = kh * 32;
        #pragma unroll 4
        for (int u0 = 0; u0 < 32; u0++) {
            int u = ub + u0;
            float wa = W1[u * NIN + n];
            float wb = W1[(NU + u) * NIN + n];
            #pragma unroll
            for (int r = 0; r < RPB; r++) {
                a[r]  = fmaf(sx[r][u], wa, a[r]);
                bs[r] = fmaf(sx[r][u], wb, bs[r]);
            }
        }
    }
    if (kh == 1) {
        #pragma unroll
        for (int r = 0; r < RPB; r++) { spA[r][n] = a[r]; spB[r][n] = bs[r]; }
    }
    __syncthreads();
    if (kh == 0) {
        float bb = (n < NIN) ? b1[n] : 0.0f;
        #pragma unroll
        for (int r = 0; r < RPB; r++) {
            g_A   [(size_t)(R0 + r) * NPD + n] = a[r] + spA[r][n];
            g_Base[(size_t)(R0 + r) * NPD + n] = bs[r] + spB[r][n] + bb;
        }
    }
}

// ---------------- kernel 4: edge phase ----------------
// Block = 2 columns x 4 subsets (8 warps). Warp (jc, sub) processes edges
// e in groups of 2, groups g = sub, sub+4, ... for BOTH batches (4 chains).
// Subset partials combine in fixed order via smem; warps 0..3 write outputs.
__global__ void __launch_bounds__(256, 3) edge_kernel(
    const float* __restrict__ xin_ext, float* __restrict__ xout_ext,
    int use_g_in, int use_g_out,
    const float* __restrict__ rel,
    const float* __restrict__ W1,      // rows 128..135 = rel weights
    const float* __restrict__ w2,
    const float* __restrict__ b2p)
{
    const float* xin  = use_g_in  ? g_x1 : xin_ext;
    float*       xout = use_g_out ? g_x1 : xout_ext;

    __shared__ float sW1c[NK * NPD];
    __shared__ float sacc[2][4][2];    // [jc][sub][batch]

    int tid = threadIdx.x, warp = tid >> 5, lane = tid & 31;

    for (int idx = tid; idx < NK * NPD; idx += 256) {
        int kk = idx / NPD, n = idx % NPD;
        sW1c[idx] = (n < NIN) ? W1[(2 * NU + kk) * NIN + n] : 0.0f;
    }
    float w2l[5];
    #pragma unroll
    for (int m = 0; m < 5; m++) {
        int n = lane + 32 * m;
        w2l[m] = (n < NIN) ? w2[n] : 0.0f;
    }
    float b2 = __ldg(b2p);
    __syncthreads();

    int jc  = warp >> 2;               // 0..1
    int sub = warp & 3;                // 0..3
    int j   = blockIdx.x * 2 + jc;
    int cnt = g_colcnt[j];
    const int* rows = g_colrows + j * NN;

    // hoist Base for (b=0,j) and (b=1,j)
    float base[2][5];
    #pragma unroll
    for (int b = 0; b < 2; b++) {
        const float* Bs = g_Base + ((size_t)(b * NN + j)) * NPD;
        #pragma unroll
        for (int m = 0; m < 5; m++) base[b][m] = Bs[lane + 32 * m];
    }

    float wacc[2] = {0.0f, 0.0f};
    for (int g = sub; 2 * g < cnt; g += 4) {
        int e0 = 2 * g;
        float vdv[2];
        float rv[2][8];
        float h[4][5];      // chain c = s*2 + b
        int iv[2];

        #pragma unroll
        for (int s = 0; s < 2; s++) {
            int e = e0 + s;
            bool v = (e < cnt);
            int i = rows[v ? e : 0];
            iv[s] = i;
            vdv[s] = v ? g_invD[i] : 0.0f;
            const float4* rp = reinterpret_cast<const float4*>(
                rel + ((size_t)i * NN + j) * NK);
            float4 r0 = rp[0], r1 = rp[1];
            rv[s][0] = r0.x; rv[s][1] = r0.y; rv[s][2] = r0.z; rv[s][3] = r0.w;
            rv[s][4] = r1.x; rv[s][5] = r1.y; rv[s][6] = r1.z; rv[s][7] = r1.w;
        }
        #pragma unroll
        for (int s = 0; s < 2; s++) {
            #pragma unroll
            for (int b = 0; b < 2; b++) {
                const float* Ar = g_A + ((size_t)(b * NN + iv[s])) * NPD;
                #pragma unroll
                for (int m = 0; m < 5; m++)
                    h[s * 2 + b][m] = Ar[lane + 32 * m] + base[b][m];
            }
        }

        #pragma unroll
        for (int kk = 0; kk < NK; kk++) {
            float w1v[5];
            #pragma unroll
            for (int m = 0; m < 5; m++)
                w1v[m] = sW1c[kk * NPD + lane + 32 * m];
            #pragma unroll
            for (int c = 0; c < 4; c++)
                #pragma unroll
                for (int m = 0; m < 5; m++)
                    h[c][m] = fmaf(rv[c >> 1][kk], w1v[m], h[c][m]);
        }

        float d[4];
        #pragma unroll
        for (int c = 0; c < 4; c++) {
            float acc = 0.0f;
            #pragma unroll
            for (int m = 0; m < 5; m++) {
                float hv = h[c][m];
                hv = fmaxf(hv, SLOPE * hv);
                acc = fmaf(hv, w2l[m], acc);
            }
            d[c] = acc;
        }
        #pragma unroll
        for (int o = 16; o > 0; o >>= 1) {
            #pragma unroll
            for (int c = 0; c < 4; c++)
                d[c] += __shfl_xor_sync(~0u, d[c], o);
        }
        #pragma unroll
        for (int c = 0; c < 4; c++) {
            int s = c >> 1, b = c & 1;
            float o2 = d[c] + b2;
            o2 = fmaxf(o2, SLOPE * o2);
            wacc[b] = fmaf(o2, vdv[s], wacc[b]);
        }
    }

    if (lane == 0) {
        sacc[jc][sub][0] = wacc[0];
        sacc[jc][sub][1] = wacc[1];
    }
    __syncthreads();

    // warps 0..3 write outputs: warp w -> (jc2 = w>>1, b = w&1)
    if (warp < 4) {
        int jc2 = warp >> 1, b = warp & 1;
        int j2 = blockIdx.x * 2 + jc2;
        float S = ((sacc[jc2][0][b] + sacc[jc2][1][b])
                 +  sacc[jc2][2][b]) + sacc[jc2][3][b];
        size_t obase = ((size_t)(b * NN + j2)) * NU;
        xout[obase + lane]      = xin[obase + lane]      * S;
        xout[obase + 32 + lane] = xin[obase + 32 + lane] * S;
    }
}

// ---------------- launch ----------------
extern "C" void kernel_launch(void* const* d_in, const int* in_sizes, int n_in,
                              void* d_out, int out_size) {
    const float* seq  = (const float*)d_in[0];
    const float* rel  = (const float*)d_in[1];
    const float* w1_1 = (const float*)d_in[2];
    const float* b1_1 = (const float*)d_in[3];
    const float* w1_2 = (const float*)d_in[4];
    const float* b1_2 = (const float*)d_in[5];
    const float* w2_1 = (const float*)d_in[6];
    const float* b2_1 = (const float*)d_in[7];
    const float* w2_2 = (const float*)d_in[8];
    const float* b2_2 = (const float*)d_in[9];
    float* out = (float*)d_out;

    maskdeg_kernel <<<NN, 256>>>(rel);
    colbuild_kernel<<<NN, 768>>>();

    const int PGRID = NB * NN / RPB;   // 384
    const int EGRID = NN / 2;          // 384 (2 columns x 4 subsets per block)

    // hop 1: seq -> g_x1 (edge kernel writes x1 directly)
    precompute_kernel<<<PGRID, PTHREADS>>>(seq, 0, w1_1, b1_1);
    edge_kernel      <<<EGRID, 256>>>(seq, nullptr, 0, 1, rel, w1_1, w1_2, b1_2);

    // hop 2: g_x1 -> out
    precompute_kernel<<<PGRID, PTHREADS>>>(nullptr, 1, w2_1, b2_1);
    edge_kernel      <<<EGRID, 256>>>(nullptr, out, 1, 0, rel, w2_1, w2_2, b2_2);
}